// round 2
// baseline (speedup 1.0000x reference)
#include <cuda_runtime.h>
#include <math.h>

// BERT-base forward: B=4, S=512, L=12, D=768, H=12, F=3072, V=30522
#define Bq 4
#define Sq 512
#define Lq 12
#define Dq 768
#define Hq 12
#define Fq 3072
#define Vq 30522
#define HDq 64
#define Tq 2048   // B*S tokens

// Workspace: x,q,k,v,t,x1 [T,D] + h [T,F]  = 60 MB
__device__ float g_ws[6 * (size_t)Tq * Dq + (size_t)Tq * Fq];

// ---------------------------------------------------------------------------
// Block-wide sum of (a,b) pairs, 256 threads
// ---------------------------------------------------------------------------
__device__ __forceinline__ float2 blockReduce2(float a, float b) {
#pragma unroll
    for (int o = 16; o > 0; o >>= 1) {
        a += __shfl_down_sync(0xffffffffu, a, o);
        b += __shfl_down_sync(0xffffffffu, b, o);
    }
    __shared__ float2 sh[8];
    int lane = threadIdx.x & 31, wid = threadIdx.x >> 5;
    if (lane == 0) sh[wid] = make_float2(a, b);
    __syncthreads();
    if (wid == 0) {
        float2 v = (lane < 8) ? sh[lane] : make_float2(0.f, 0.f);
#pragma unroll
        for (int o = 4; o > 0; o >>= 1) {
            v.x += __shfl_down_sync(0xffffffffu, v.x, o);
            v.y += __shfl_down_sync(0xffffffffu, v.y, o);
        }
        if (lane == 0) sh[0] = v;
    }
    __syncthreads();
    return sh[0];
}

// ---------------------------------------------------------------------------
// Embedding + LayerNorm: one block per token, 256 threads (3 elems each)
// ---------------------------------------------------------------------------
__global__ void embed_ln_kernel(const int* __restrict__ ids,
                                const float* __restrict__ wemb,
                                const float* __restrict__ pemb,
                                const float* __restrict__ semb,
                                const float* __restrict__ g,
                                const float* __restrict__ bta,
                                float* __restrict__ x) {
    int t = blockIdx.x;
    int s = t & (Sq - 1);
    int id = ids[t];
    float v[3];
    float sum = 0.f, sq = 0.f;
#pragma unroll
    for (int i = 0; i < 3; i++) {
        int d = threadIdx.x + i * 256;
        float val = wemb[(size_t)id * Dq + d] + pemb[(size_t)s * Dq + d] + semb[d];
        v[i] = val;
        sum += val;
        sq += val * val;
    }
    float2 r = blockReduce2(sum, sq);
    float mu = r.x * (1.0f / Dq);
    float var = r.y * (1.0f / Dq) - mu * mu;
    float rstd = rsqrtf(var + 1e-5f);
#pragma unroll
    for (int i = 0; i < 3; i++) {
        int d = threadIdx.x + i * 256;
        x[(size_t)t * Dq + d] = (v[i] - mu) * rstd * g[d] + bta[d];
    }
}

// ---------------------------------------------------------------------------
// out = LayerNorm(a + bvec) * g + beta : one block per token
// ---------------------------------------------------------------------------
__global__ void add_ln_kernel(const float* __restrict__ a,
                              const float* __restrict__ bvec,
                              const float* __restrict__ g,
                              const float* __restrict__ bta,
                              float* __restrict__ out) {
    int t = blockIdx.x;
    float v[3];
    float sum = 0.f, sq = 0.f;
#pragma unroll
    for (int i = 0; i < 3; i++) {
        int d = threadIdx.x + i * 256;
        float val = a[(size_t)t * Dq + d] + bvec[(size_t)t * Dq + d];
        v[i] = val;
        sum += val;
        sq += val * val;
    }
    float2 r = blockReduce2(sum, sq);
    float mu = r.x * (1.0f / Dq);
    float var = r.y * (1.0f / Dq) - mu * mu;
    float rstd = rsqrtf(var + 1e-5f);
#pragma unroll
    for (int i = 0; i < 3; i++) {
        int d = threadIdx.x + i * 256;
        out[(size_t)t * Dq + d] = (v[i] - mu) * rstd * g[d] + bta[d];
    }
}

// ---------------------------------------------------------------------------
// SGEMM: C[M,N] = A[M,K] @ B[K,N]  (row-major). 128x128x8 tiles, 8x8/thread.
// EPI: 0=none, 1=+bias, 2=+bias then exact GELU.  M % 128 == 0, K % 8 == 0.
// ---------------------------------------------------------------------------
template <int EPI>
__global__ void __launch_bounds__(256)
sgemm_kernel(const float* __restrict__ A, const float* __restrict__ Bm,
             const float* __restrict__ bias, float* __restrict__ C,
             int M, int N, int K) {
    __shared__ float As[8][128];
    __shared__ float Bs[8][128];
    int tid = threadIdx.x;
    int tx = tid & 15, ty = tid >> 4;
    int row0 = blockIdx.y * 128, col0 = blockIdx.x * 128;

    int aRow = tid >> 1;
    int aCol = (tid & 1) * 4;
    int bRow = tid >> 5;
    int bCol = (tid & 31) * 4;

    const float* Ap = A + (size_t)(row0 + aRow) * K + aCol;
    const float* Bp = Bm + (size_t)bRow * N + col0 + bCol;
    bool bIn = (col0 + bCol + 3) < N;

    float acc[8][8] = {};

    for (int k0 = 0; k0 < K; k0 += 8) {
        float4 av = *(const float4*)(Ap + k0);
        As[aCol + 0][aRow] = av.x;
        As[aCol + 1][aRow] = av.y;
        As[aCol + 2][aRow] = av.z;
        As[aCol + 3][aRow] = av.w;

        const float* bp = Bp + (size_t)k0 * N;
        float b0, b1, b2, b3;
        if (bIn) {
            b0 = bp[0]; b1 = bp[1]; b2 = bp[2]; b3 = bp[3];
        } else {
            int c = col0 + bCol;
            b0 = (c + 0 < N) ? bp[0] : 0.f;
            b1 = (c + 1 < N) ? bp[1] : 0.f;
            b2 = (c + 2 < N) ? bp[2] : 0.f;
            b3 = (c + 3 < N) ? bp[3] : 0.f;
        }
        Bs[bRow][bCol + 0] = b0;
        Bs[bRow][bCol + 1] = b1;
        Bs[bRow][bCol + 2] = b2;
        Bs[bRow][bCol + 3] = b3;
        __syncthreads();

#pragma unroll
        for (int kk = 0; kk < 8; kk++) {
            float ar[8], br[8];
            *(float4*)&ar[0] = *(const float4*)&As[kk][ty * 8];
            *(float4*)&ar[4] = *(const float4*)&As[kk][ty * 8 + 4];
            *(float4*)&br[0] = *(const float4*)&Bs[kk][tx * 8];
            *(float4*)&br[4] = *(const float4*)&Bs[kk][tx * 8 + 4];
#pragma unroll
            for (int i = 0; i < 8; i++)
#pragma unroll
                for (int j = 0; j < 8; j++)
                    acc[i][j] += ar[i] * br[j];
        }
        __syncthreads();
    }

#pragma unroll
    for (int i = 0; i < 8; i++) {
        int r = row0 + ty * 8 + i;
#pragma unroll
        for (int j = 0; j < 8; j++) {
            int c = col0 + tx * 8 + j;
            if (c < N) {
                float vv = acc[i][j];
                if (EPI >= 1) vv += bias[c];
                if (EPI == 2) vv = 0.5f * vv * (1.0f + erff(vv * 0.70710678118654752f));
                C[(size_t)r * N + c] = vv;
            }
        }
    }
}

// ---------------------------------------------------------------------------
// Attention scores: out[bh, q, k] = scale * dot(q_vec, k_vec), mask -> -inf
// grid (S/64, S/64, B*H), 256 threads, 64x64 tile, full HD=64 in smem
// ---------------------------------------------------------------------------
__global__ void __launch_bounds__(256)
attn_scores_kernel(const float* __restrict__ q, const float* __restrict__ k,
                   const int* __restrict__ mask, float* __restrict__ out) {
    int bh = blockIdx.z;
    int b = bh / Hq, h = bh % Hq;
    __shared__ float Qs[64][65];
    __shared__ float Ks[64][65];
    int tid = threadIdx.x;
    int q0 = blockIdx.y * 64, k0 = blockIdx.x * 64;

#pragma unroll
    for (int i = 0; i < 4; i++) {
        int idx = tid + i * 256;
        int r = idx >> 4;
        int c4 = (idx & 15) * 4;
        float4 qv = *(const float4*)(q + (size_t)(b * Sq + q0 + r) * Dq + h * HDq + c4);
        Qs[r][c4 + 0] = qv.x; Qs[r][c4 + 1] = qv.y; Qs[r][c4 + 2] = qv.z; Qs[r][c4 + 3] = qv.w;
        float4 kv = *(const float4*)(k + (size_t)(b * Sq + k0 + r) * Dq + h * HDq + c4);
        Ks[r][c4 + 0] = kv.x; Ks[r][c4 + 1] = kv.y; Ks[r][c4 + 2] = kv.z; Ks[r][c4 + 3] = kv.w;
    }
    __syncthreads();

    int tx = tid & 15, ty = tid >> 4;
    float acc[4][4] = {};
#pragma unroll 8
    for (int d = 0; d < 64; d++) {
        float aq[4], bk[4];
#pragma unroll
        for (int i = 0; i < 4; i++) aq[i] = Qs[ty * 4 + i][d];
#pragma unroll
        for (int j = 0; j < 4; j++) bk[j] = Ks[tx * 4 + j][d];
#pragma unroll
        for (int i = 0; i < 4; i++)
#pragma unroll
            for (int j = 0; j < 4; j++)
                acc[i][j] += aq[i] * bk[j];
    }

    const float scale = 0.03608439182435161f;  // 1/sqrt(D=768)
#pragma unroll
    for (int j = 0; j < 4; j++) {
        int kc = k0 + tx * 4 + j;
        bool masked = (mask[b * Sq + kc] == 0);
#pragma unroll
        for (int i = 0; i < 4; i++) {
            int qr = q0 + ty * 4 + i;
            float vv = acc[i][j] * scale;
            if (masked) vv = -INFINITY;
            out[((size_t)bh * Sq + qr) * Sq + kc] = vv;
        }
    }
}

// ---------------------------------------------------------------------------
// In-place softmax over last dim (512). One warp per row, 16 elems/lane.
// ---------------------------------------------------------------------------
__global__ void softmax_kernel(float* __restrict__ p) {
    int row = blockIdx.x * 4 + (threadIdx.x >> 5);
    int lane = threadIdx.x & 31;
    float* r = p + (size_t)row * Sq;
    float v[16];
    float m = -INFINITY;
#pragma unroll
    for (int i = 0; i < 16; i++) {
        v[i] = r[lane + i * 32];
        m = fmaxf(m, v[i]);
    }
#pragma unroll
    for (int o = 16; o > 0; o >>= 1) m = fmaxf(m, __shfl_xor_sync(0xffffffffu, m, o));
    float s = 0.f;
#pragma unroll
    for (int i = 0; i < 16; i++) {
        v[i] = __expf(v[i] - m);
        s += v[i];
    }
#pragma unroll
    for (int o = 16; o > 0; o >>= 1) s += __shfl_xor_sync(0xffffffffu, s, o);
    float inv = 1.0f / s;
#pragma unroll
    for (int i = 0; i < 16; i++) r[lane + i * 32] = v[i] * inv;
}

// ---------------------------------------------------------------------------
// o[b, q, h*64+d] = sum_k P[bh, q, k] * V[b, k, h*64+d]
// grid (1, S/64, B*H), 64x64 output tile, K-loop in chunks of 32
// ---------------------------------------------------------------------------
__global__ void __launch_bounds__(256)
attn_av_kernel(const float* __restrict__ p, const float* __restrict__ v,
               float* __restrict__ o) {
    int bh = blockIdx.z;
    int b = bh / Hq, h = bh % Hq;
    int q0 = blockIdx.y * 64;
    __shared__ float Ps[64][33];
    __shared__ float Vs[32][64];
    int tid = threadIdx.x;
    int tx = tid & 15, ty = tid >> 4;
    float acc[4][4] = {};

    for (int k0 = 0; k0 < Sq; k0 += 32) {
#pragma unroll
        for (int i = 0; i < 2; i++) {
            int idx = tid + i * 256;
            int pr = idx >> 3, pc4 = (idx & 7) * 4;
            float4 pv = *(const float4*)(p + ((size_t)bh * Sq + q0 + pr) * Sq + k0 + pc4);
            Ps[pr][pc4 + 0] = pv.x; Ps[pr][pc4 + 1] = pv.y;
            Ps[pr][pc4 + 2] = pv.z; Ps[pr][pc4 + 3] = pv.w;
            int vr = idx >> 4, vc4 = (idx & 15) * 4;
            float4 vv = *(const float4*)(v + (size_t)(b * Sq + k0 + vr) * Dq + h * HDq + vc4);
            *(float4*)&Vs[vr][vc4] = vv;
        }
        __syncthreads();
#pragma unroll 8
        for (int kk = 0; kk < 32; kk++) {
            float a4[4];
#pragma unroll
            for (int i = 0; i < 4; i++) a4[i] = Ps[ty * 4 + i][kk];
            float4 bv = *(const float4*)&Vs[kk][tx * 4];
            float bb[4] = {bv.x, bv.y, bv.z, bv.w};
#pragma unroll
            for (int i = 0; i < 4; i++)
#pragma unroll
                for (int j = 0; j < 4; j++)
                    acc[i][j] += a4[i] * bb[j];
        }
        __syncthreads();
    }

#pragma unroll
    for (int i = 0; i < 4; i++) {
        int qr = q0 + ty * 4 + i;
#pragma unroll
        for (int j = 0; j < 4; j++)
            o[(size_t)(b * Sq + qr) * Dq + h * HDq + tx * 4 + j] = acc[i][j];
    }
}

// ---------------------------------------------------------------------------
// Host orchestration (graph-capturable: kernel launches only)
// ---------------------------------------------------------------------------
extern "C" void kernel_launch(void* const* d_in, const int* in_sizes, int n_in,
                              void* d_out, int out_size) {
    const int*   ids  = (const int*)d_in[0];
    const int*   mask = (const int*)d_in[1];
    const float* wemb = (const float*)d_in[2];
    const float* pemb = (const float*)d_in[3];
    const float* semb = (const float*)d_in[4];
    const float* elng = (const float*)d_in[5];
    const float* elnb = (const float*)d_in[6];
    const float* Wq   = (const float*)d_in[7];
    const float* Wk   = (const float*)d_in[8];
    const float* Wv   = (const float*)d_in[9];
    const float* Wo   = (const float*)d_in[10];
    const float* f1w  = (const float*)d_in[11];
    const float* f1b  = (const float*)d_in[12];
    const float* f2w  = (const float*)d_in[13];
    const float* f2b  = (const float*)d_in[14];
    const float* l1g  = (const float*)d_in[15];
    const float* l1b  = (const float*)d_in[16];
    const float* l2g  = (const float*)d_in[17];
    const float* l2b  = (const float*)d_in[18];
    const float* outw = (const float*)d_in[19];
    const float* outb = (const float*)d_in[20];

    float* ws = nullptr;
    cudaGetSymbolAddress((void**)&ws, g_ws);
    float* x  = ws;
    float* q  = ws + 1 * (size_t)Tq * Dq;
    float* kb = ws + 2 * (size_t)Tq * Dq;
    float* vb = ws + 3 * (size_t)Tq * Dq;
    float* tb = ws + 4 * (size_t)Tq * Dq;
    float* x1 = ws + 5 * (size_t)Tq * Dq;
    float* hb = ws + 6 * (size_t)Tq * Dq;

    float* logits = (float*)d_out;                       // [B*S, V]
    float* attn   = logits + (size_t)Tq * Vq;            // [L, B*H, S, S]

    embed_ln_kernel<<<Tq, 256>>>(ids, wemb, pemb, semb, elng, elnb, x);

    for (int l = 0; l < Lq; l++) {
        float* slab = attn + (size_t)l * Bq * Hq * Sq * Sq;
        dim3 gDD(Dq / 128, Tq / 128);  // (6,16)

        sgemm_kernel<0><<<gDD, 256>>>(x, Wq + (size_t)l * Dq * Dq, nullptr, q,  Tq, Dq, Dq);
        sgemm_kernel<0><<<gDD, 256>>>(x, Wk + (size_t)l * Dq * Dq, nullptr, kb, Tq, Dq, Dq);
        sgemm_kernel<0><<<gDD, 256>>>(x, Wv + (size_t)l * Dq * Dq, nullptr, vb, Tq, Dq, Dq);

        attn_scores_kernel<<<dim3(Sq / 64, Sq / 64, Bq * Hq), 256>>>(q, kb, mask, slab);
        softmax_kernel<<<Bq * Hq * Sq / 4, 128>>>(slab);
        attn_av_kernel<<<dim3(1, Sq / 64, Bq * Hq), 256>>>(slab, vb, tb);

        sgemm_kernel<0><<<gDD, 256>>>(tb, Wo + (size_t)l * Dq * Dq, nullptr, q, Tq, Dq, Dq);
        add_ln_kernel<<<Tq, 256>>>(x, q, l1g + (size_t)l * Dq, l1b + (size_t)l * Dq, x1);

        sgemm_kernel<2><<<dim3(Fq / 128, Tq / 128), 256>>>(
            x1, f1w + (size_t)l * Dq * Fq, f1b + (size_t)l * Fq, hb, Tq, Fq, Dq);
        sgemm_kernel<1><<<dim3(Dq / 128, Tq / 128), 256>>>(
            hb, f2w + (size_t)l * Fq * Dq, f2b + (size_t)l * Dq, tb, Tq, Dq, Fq);
        add_ln_kernel<<<Tq, 256>>>(x1, tb, l2g + (size_t)l * Dq, l2b + (size_t)l * Dq, x);
    }

    sgemm_kernel<1><<<dim3((Vq + 127) / 128, Tq / 128), 256>>>(
        x, outw, outb, logits, Tq, Vq, Dq);
}

// round 5
// speedup vs baseline: 1.9836x; 1.9836x over previous
#include <cuda_runtime.h>
#include <mma.h>
#include <math.h>

using namespace nvcuda;

// BERT-base forward: B=4, S=512, L=12, D=768, H=12, F=3072, V=30522
#define Bq 4
#define Sq 512
#define Lq 12
#define Dq 768
#define Hq 12
#define Fq 3072
#define Vq 30522
#define HDq 64
#define Tq 2048   // B*S tokens

// Workspace: x,q,k,v,t,x1 [T,D] + h [T,F]  = 60 MB
__device__ float g_ws[6 * (size_t)Tq * Dq + (size_t)Tq * Fq];

__device__ __forceinline__ float T32(float x) { return wmma::__float_to_tf32(x); }

// ---------------------------------------------------------------------------
// Block-wide sum of (a,b) pairs, 256 threads
// ---------------------------------------------------------------------------
__device__ __forceinline__ float2 blockReduce2(float a, float b) {
#pragma unroll
    for (int o = 16; o > 0; o >>= 1) {
        a += __shfl_down_sync(0xffffffffu, a, o);
        b += __shfl_down_sync(0xffffffffu, b, o);
    }
    __shared__ float2 sh[8];
    int lane = threadIdx.x & 31, wid = threadIdx.x >> 5;
    if (lane == 0) sh[wid] = make_float2(a, b);
    __syncthreads();
    if (wid == 0) {
        float2 v = (lane < 8) ? sh[lane] : make_float2(0.f, 0.f);
#pragma unroll
        for (int o = 4; o > 0; o >>= 1) {
            v.x += __shfl_down_sync(0xffffffffu, v.x, o);
            v.y += __shfl_down_sync(0xffffffffu, v.y, o);
        }
        if (lane == 0) sh[0] = v;
    }
    __syncthreads();
    return sh[0];
}

// ---------------------------------------------------------------------------
// Embedding + LayerNorm: one block per token, 256 threads (3 elems each)
// ---------------------------------------------------------------------------
__global__ void embed_ln_kernel(const int* __restrict__ ids,
                                const float* __restrict__ wemb,
                                const float* __restrict__ pemb,
                                const float* __restrict__ semb,
                                const float* __restrict__ g,
                                const float* __restrict__ bta,
                                float* __restrict__ x) {
    int t = blockIdx.x;
    int s = t & (Sq - 1);
    int id = ids[t];
    float v[3];
    float sum = 0.f, sq = 0.f;
#pragma unroll
    for (int i = 0; i < 3; i++) {
        int d = threadIdx.x + i * 256;
        float val = wemb[(size_t)id * Dq + d] + pemb[(size_t)s * Dq + d] + semb[d];
        v[i] = val;
        sum += val;
        sq += val * val;
    }
    float2 r = blockReduce2(sum, sq);
    float mu = r.x * (1.0f / Dq);
    float var = r.y * (1.0f / Dq) - mu * mu;
    float rstd = rsqrtf(var + 1e-5f);
#pragma unroll
    for (int i = 0; i < 3; i++) {
        int d = threadIdx.x + i * 256;
        x[(size_t)t * Dq + d] = (v[i] - mu) * rstd * g[d] + bta[d];
    }
}

// ---------------------------------------------------------------------------
// out = LayerNorm(a + bvec) * g + beta : one block per token
// ---------------------------------------------------------------------------
__global__ void add_ln_kernel(const float* __restrict__ a,
                              const float* __restrict__ bvec,
                              const float* __restrict__ g,
                              const float* __restrict__ bta,
                              float* __restrict__ out) {
    int t = blockIdx.x;
    float v[3];
    float sum = 0.f, sq = 0.f;
#pragma unroll
    for (int i = 0; i < 3; i++) {
        int d = threadIdx.x + i * 256;
        float val = a[(size_t)t * Dq + d] + bvec[(size_t)t * Dq + d];
        v[i] = val;
        sum += val;
        sq += val * val;
    }
    float2 r = blockReduce2(sum, sq);
    float mu = r.x * (1.0f / Dq);
    float var = r.y * (1.0f / Dq) - mu * mu;
    float rstd = rsqrtf(var + 1e-5f);
#pragma unroll
    for (int i = 0; i < 3; i++) {
        int d = threadIdx.x + i * 256;
        out[(size_t)t * Dq + d] = (v[i] - mu) * rstd * g[d] + bta[d];
    }
}

// ---------------------------------------------------------------------------
// TF32 WMMA GEMM body: C[M,N] = A[M,K] @ B[K,N], row-major.
// 128x128 block tile, BK=32, 8 warps (4 in M x 2 in N), warp tile 32x64.
// EPI: 0=none, 1=+bias, 2=+bias then exact GELU. M%128==0, K%32==0, N any.
// ALIGN4: B rows are 16B-aligned (N % 4 == 0) -> float4 loads.
//         otherwise N must be even -> float2 loads (8B-aligned rows).
// ---------------------------------------------------------------------------
template <int EPI, bool ALIGN4>
__device__ __forceinline__ void gemm_body(const float* __restrict__ A,
                                          const float* __restrict__ Bm,
                                          const float* __restrict__ bias,
                                          float* __restrict__ C,
                                          int M, int N, int K) {
    __shared__ float As[128][36];
    __shared__ float Bs[32][132];
    __shared__ float Cs[8][16][20];

    int tid = threadIdx.x;
    int row0 = blockIdx.y * 128, col0 = blockIdx.x * 128;
    int warp = tid >> 5, lane = tid & 31;
    int wm = warp & 3, wn = warp >> 2;

    wmma::fragment<wmma::accumulator, 16, 16, 8, float> acc[2][4];
#pragma unroll
    for (int i = 0; i < 2; i++)
#pragma unroll
        for (int j = 0; j < 4; j++)
            wmma::fill_fragment(acc[i][j], 0.0f);

    int aRow = tid >> 3;
    int aCol = (tid & 7) * 4;
    int bRowBase = tid >> 5;
    int bCol = (tid & 31) * 4;

    for (int k0 = 0; k0 < K; k0 += 32) {
#pragma unroll
        for (int it = 0; it < 4; it++) {
            int r = aRow + it * 32;
            float4 v = *(const float4*)(A + (size_t)(row0 + r) * K + k0 + aCol);
            As[r][aCol + 0] = T32(v.x);
            As[r][aCol + 1] = T32(v.y);
            As[r][aCol + 2] = T32(v.z);
            As[r][aCol + 3] = T32(v.w);
        }
#pragma unroll
        for (int it = 0; it < 4; it++) {
            int r = bRowBase + it * 8;
            const float* p = Bm + (size_t)(k0 + r) * N + col0 + bCol;
            if (ALIGN4) {
                float4 v = *(const float4*)p;
                Bs[r][bCol + 0] = T32(v.x);
                Bs[r][bCol + 1] = T32(v.y);
                Bs[r][bCol + 2] = T32(v.z);
                Bs[r][bCol + 3] = T32(v.w);
            } else {
                int c = col0 + bCol;
                if (c + 3 < N) {
                    // rows are 8B-aligned (N even), col multiple of 4 -> float2 ok
                    float2 v0 = *(const float2*)p;
                    float2 v1 = *(const float2*)(p + 2);
                    Bs[r][bCol + 0] = T32(v0.x);
                    Bs[r][bCol + 1] = T32(v0.y);
                    Bs[r][bCol + 2] = T32(v1.x);
                    Bs[r][bCol + 3] = T32(v1.y);
                } else {
#pragma unroll
                    for (int e = 0; e < 4; e++)
                        Bs[r][bCol + e] = (c + e < N) ? T32(p[e]) : 0.f;
                }
            }
        }
        __syncthreads();

#pragma unroll
        for (int kk = 0; kk < 4; kk++) {
            wmma::fragment<wmma::matrix_a, 16, 16, 8, wmma::precision::tf32, wmma::row_major> af[2];
            wmma::fragment<wmma::matrix_b, 16, 16, 8, wmma::precision::tf32, wmma::row_major> bf[4];
#pragma unroll
            for (int i = 0; i < 2; i++)
                wmma::load_matrix_sync(af[i], &As[wm * 32 + i * 16][kk * 8], 36);
#pragma unroll
            for (int j = 0; j < 4; j++)
                wmma::load_matrix_sync(bf[j], &Bs[kk * 8][wn * 64 + j * 16], 132);
#pragma unroll
            for (int i = 0; i < 2; i++)
#pragma unroll
                for (int j = 0; j < 4; j++)
                    wmma::mma_sync(acc[i][j], af[i], bf[j], acc[i][j]);
        }
        __syncthreads();
    }

    int rr = lane >> 1, cc = (lane & 1) * 8;
#pragma unroll
    for (int i = 0; i < 2; i++) {
#pragma unroll
        for (int j = 0; j < 4; j++) {
            wmma::store_matrix_sync(&Cs[warp][0][0], acc[i][j], 20, wmma::mem_row_major);
            __syncwarp();
            int r = row0 + wm * 32 + i * 16 + rr;
            int c0l = col0 + wn * 64 + j * 16 + cc;
            float* dst = C + (size_t)r * N + c0l;
#pragma unroll
            for (int e = 0; e < 8; e++) {
                int c = c0l + e;
                if (ALIGN4 || c < N) {
                    float vv = Cs[warp][rr][cc + e];
                    if (EPI >= 1) vv += bias[c];
                    if (EPI == 2) vv = 0.5f * vv * (1.0f + erff(vv * 0.70710678118654752f));
                    dst[e] = vv;
                }
            }
            __syncwarp();
        }
    }
}

template <int EPI, bool ALIGN4>
__global__ void __launch_bounds__(256)
gemm_tf32_kernel(const float* __restrict__ A, const float* __restrict__ Bm,
                 const float* __restrict__ bias, float* __restrict__ C,
                 int M, int N, int K) {
    gemm_body<EPI, ALIGN4>(A, Bm, bias, C, M, N, K);
}

// Batched QKV: blockIdx.z selects weight + output (q/k/v contiguous in ws)
__global__ void __launch_bounds__(256)
gemm_qkv_kernel(const float* __restrict__ A, const float* __restrict__ w0,
                const float* __restrict__ w1, const float* __restrict__ w2,
                float* __restrict__ c0) {
    const float* Bm = (blockIdx.z == 0) ? w0 : (blockIdx.z == 1) ? w1 : w2;
    float* C = c0 + (size_t)blockIdx.z * Tq * Dq;
    gemm_body<0, true>(A, Bm, nullptr, C, Tq, Dq, Dq);
}

// ---------------------------------------------------------------------------
// Attention scores (TF32 wmma): out[bh,q,k] = scale*dot(q,k), mask -> -inf
// grid (S/64, S/64, B*H), 256 threads. 8 warps: 4 in M (16 rows) x 2 in N (32 cols)
// ---------------------------------------------------------------------------
__global__ void __launch_bounds__(256)
attn_scores_tf32(const float* __restrict__ q, const float* __restrict__ k,
                 const int* __restrict__ mask, float* __restrict__ out) {
    __shared__ float Qs[64][68];
    __shared__ float Ks[64][68];
    __shared__ float Cs[8][16][20];
    int bh = blockIdx.z;
    int b = bh / Hq, h = bh % Hq;
    int q0 = blockIdx.y * 64, k0 = blockIdx.x * 64;
    int tid = threadIdx.x;

#pragma unroll
    for (int i = 0; i < 4; i++) {
        int idx = tid + i * 256;
        int r = idx >> 4;
        int c4 = (idx & 15) * 4;
        float4 qv = *(const float4*)(q + (size_t)(b * Sq + q0 + r) * Dq + h * HDq + c4);
        Qs[r][c4 + 0] = T32(qv.x); Qs[r][c4 + 1] = T32(qv.y);
        Qs[r][c4 + 2] = T32(qv.z); Qs[r][c4 + 3] = T32(qv.w);
        float4 kv = *(const float4*)(k + (size_t)(b * Sq + k0 + r) * Dq + h * HDq + c4);
        Ks[r][c4 + 0] = T32(kv.x); Ks[r][c4 + 1] = T32(kv.y);
        Ks[r][c4 + 2] = T32(kv.z); Ks[r][c4 + 3] = T32(kv.w);
    }
    __syncthreads();

    int warp = tid >> 5, lane = tid & 31;
    int wm = warp & 3, wn = warp >> 2;

    wmma::fragment<wmma::accumulator, 16, 16, 8, float> acc[2];
    wmma::fill_fragment(acc[0], 0.0f);
    wmma::fill_fragment(acc[1], 0.0f);

#pragma unroll
    for (int kk = 0; kk < 8; kk++) {
        wmma::fragment<wmma::matrix_a, 16, 16, 8, wmma::precision::tf32, wmma::row_major> af;
        wmma::load_matrix_sync(af, &Qs[wm * 16][kk * 8], 68);
#pragma unroll
        for (int j = 0; j < 2; j++) {
            wmma::fragment<wmma::matrix_b, 16, 16, 8, wmma::precision::tf32, wmma::col_major> bf;
            wmma::load_matrix_sync(bf, &Ks[wn * 32 + j * 16][kk * 8], 68);
            wmma::mma_sync(acc[j], af, bf, acc[j]);
        }
    }

    const float scale = 0.03608439182435161f;  // 1/sqrt(D=768)
    int rr = lane >> 1, cc = (lane & 1) * 8;
#pragma unroll
    for (int j = 0; j < 2; j++) {
        wmma::store_matrix_sync(&Cs[warp][0][0], acc[j], 20, wmma::mem_row_major);
        __syncwarp();
        int qr = q0 + wm * 16 + rr;
        int kc0 = k0 + wn * 32 + j * 16 + cc;
        float* dst = out + ((size_t)bh * Sq + qr) * Sq + kc0;
#pragma unroll
        for (int e = 0; e < 8; e++) {
            float vv = Cs[warp][rr][cc + e] * scale;
            if (mask[b * Sq + kc0 + e] == 0) vv = -INFINITY;
            dst[e] = vv;
        }
        __syncwarp();
    }
}

// ---------------------------------------------------------------------------
// In-place softmax over last dim (512). One warp per row, 16 elems/lane.
// ---------------------------------------------------------------------------
__global__ void softmax_kernel(float* __restrict__ p) {
    int row = blockIdx.x * 4 + (threadIdx.x >> 5);
    int lane = threadIdx.x & 31;
    float* r = p + (size_t)row * Sq;
    float v[16];
    float m = -INFINITY;
#pragma unroll
    for (int i = 0; i < 16; i++) {
        v[i] = r[lane + i * 32];
        m = fmaxf(m, v[i]);
    }
#pragma unroll
    for (int o = 16; o > 0; o >>= 1) m = fmaxf(m, __shfl_xor_sync(0xffffffffu, m, o));
    float s = 0.f;
#pragma unroll
    for (int i = 0; i < 16; i++) {
        v[i] = __expf(v[i] - m);
        s += v[i];
    }
#pragma unroll
    for (int o = 16; o > 0; o >>= 1) s += __shfl_xor_sync(0xffffffffu, s, o);
    float inv = 1.0f / s;
#pragma unroll
    for (int i = 0; i < 16; i++) r[lane + i * 32] = v[i] * inv;
}

// ---------------------------------------------------------------------------
// o[b,q,h*64+d] = sum_k P[bh,q,k] * V[b,k,h*64+d]   (TF32 wmma)
// grid (1, S/64, B*H). 8 warps: 4 in M x 2 in N (32 d-cols each)
// ---------------------------------------------------------------------------
__global__ void __launch_bounds__(256)
attn_av_tf32(const float* __restrict__ p, const float* __restrict__ v,
             float* __restrict__ o) {
    __shared__ float Ps[64][36];
    __shared__ float Vs[32][68];
    __shared__ float Cs[8][16][20];
    int bh = blockIdx.z;
    int b = bh / Hq, h = bh % Hq;
    int q0 = blockIdx.y * 64;
    int tid = threadIdx.x;
    int warp = tid >> 5, lane = tid & 31;
    int wm = warp & 3, wn = warp >> 2;

    wmma::fragment<wmma::accumulator, 16, 16, 8, float> acc[2];
    wmma::fill_fragment(acc[0], 0.0f);
    wmma::fill_fragment(acc[1], 0.0f);

    for (int k0 = 0; k0 < Sq; k0 += 32) {
#pragma unroll
        for (int i = 0; i < 2; i++) {
            int idx = tid + i * 256;
            int pr = idx >> 3, pc4 = (idx & 7) * 4;
            float4 pv = *(const float4*)(p + ((size_t)bh * Sq + q0 + pr) * Sq + k0 + pc4);
            Ps[pr][pc4 + 0] = T32(pv.x); Ps[pr][pc4 + 1] = T32(pv.y);
            Ps[pr][pc4 + 2] = T32(pv.z); Ps[pr][pc4 + 3] = T32(pv.w);
            int vr = idx >> 4, vc4 = (idx & 15) * 4;
            float4 vv = *(const float4*)(v + (size_t)(b * Sq + k0 + vr) * Dq + h * HDq + vc4);
            Vs[vr][vc4 + 0] = T32(vv.x); Vs[vr][vc4 + 1] = T32(vv.y);
            Vs[vr][vc4 + 2] = T32(vv.z); Vs[vr][vc4 + 3] = T32(vv.w);
        }
        __syncthreads();
#pragma unroll
        for (int kk = 0; kk < 4; kk++) {
            wmma::fragment<wmma::matrix_a, 16, 16, 8, wmma::precision::tf32, wmma::row_major> af;
            wmma::load_matrix_sync(af, &Ps[wm * 16][kk * 8], 36);
#pragma unroll
            for (int j = 0; j < 2; j++) {
                wmma::fragment<wmma::matrix_b, 16, 16, 8, wmma::precision::tf32, wmma::row_major> bf;
                wmma::load_matrix_sync(bf, &Vs[kk * 8][wn * 32 + j * 16], 68);
                wmma::mma_sync(acc[j], af, bf, acc[j]);
            }
        }
        __syncthreads();
    }

    int rr = lane >> 1, cc = (lane & 1) * 8;
#pragma unroll
    for (int j = 0; j < 2; j++) {
        wmma::store_matrix_sync(&Cs[warp][0][0], acc[j], 20, wmma::mem_row_major);
        __syncwarp();
        int qr = q0 + wm * 16 + rr;
        int dc = h * HDq + wn * 32 + j * 16 + cc;
        float* dst = o + (size_t)(b * Sq + qr) * Dq + dc;
#pragma unroll
        for (int e = 0; e < 8; e++) dst[e] = Cs[warp][rr][cc + e];
        __syncwarp();
    }
}

// ---------------------------------------------------------------------------
// Host orchestration (graph-capturable: kernel launches only)
// ---------------------------------------------------------------------------
extern "C" void kernel_launch(void* const* d_in, const int* in_sizes, int n_in,
                              void* d_out, int out_size) {
    const int*   ids  = (const int*)d_in[0];
    const int*   mask = (const int*)d_in[1];
    const float* wemb = (const float*)d_in[2];
    const float* pemb = (const float*)d_in[3];
    const float* semb = (const float*)d_in[4];
    const float* elng = (const float*)d_in[5];
    const float* elnb = (const float*)d_in[6];
    const float* Wq   = (const float*)d_in[7];
    const float* Wk   = (const float*)d_in[8];
    const float* Wv   = (const float*)d_in[9];
    const float* Wo   = (const float*)d_in[10];
    const float* f1w  = (const float*)d_in[11];
    const float* f1b  = (const float*)d_in[12];
    const float* f2w  = (const float*)d_in[13];
    const float* f2b  = (const float*)d_in[14];
    const float* l1g  = (const float*)d_in[15];
    const float* l1b  = (const float*)d_in[16];
    const float* l2g  = (const float*)d_in[17];
    const float* l2b  = (const float*)d_in[18];
    const float* outw = (const float*)d_in[19];
    const float* outb = (const float*)d_in[20];

    float* ws = nullptr;
    cudaGetSymbolAddress((void**)&ws, g_ws);
    float* x  = ws;
    float* q  = ws + 1 * (size_t)Tq * Dq;
    float* kb = ws + 2 * (size_t)Tq * Dq;
    float* vb = ws + 3 * (size_t)Tq * Dq;
    float* tb = ws + 4 * (size_t)Tq * Dq;
    float* x1 = ws + 5 * (size_t)Tq * Dq;
    float* hb = ws + 6 * (size_t)Tq * Dq;

    float* logits = (float*)d_out;                       // [B*S, V]
    float* attn   = logits + (size_t)Tq * Vq;            // [L, B*H, S, S]

    embed_ln_kernel<<<Tq, 256>>>(ids, wemb, pemb, semb, elng, elnb, x);

    for (int l = 0; l < Lq; l++) {
        float* slab = attn + (size_t)l * Bq * Hq * Sq * Sq;
        dim3 gDD(Dq / 128, Tq / 128);  // (6,16)

        gemm_qkv_kernel<<<dim3(Dq / 128, Tq / 128, 3), 256>>>(
            x, Wq + (size_t)l * Dq * Dq, Wk + (size_t)l * Dq * Dq,
            Wv + (size_t)l * Dq * Dq, q);

        attn_scores_tf32<<<dim3(Sq / 64, Sq / 64, Bq * Hq), 256>>>(q, kb, mask, slab);
        softmax_kernel<<<Bq * Hq * Sq / 4, 128>>>(slab);
        attn_av_tf32<<<dim3(1, Sq / 64, Bq * Hq), 256>>>(slab, vb, tb);

        gemm_tf32_kernel<0, true><<<gDD, 256>>>(tb, Wo + (size_t)l * Dq * Dq, nullptr, q, Tq, Dq, Dq);
        add_ln_kernel<<<Tq, 256>>>(x, q, l1g + (size_t)l * Dq, l1b + (size_t)l * Dq, x1);

        gemm_tf32_kernel<2, true><<<dim3(Fq / 128, Tq / 128), 256>>>(
            x1, f1w + (size_t)l * Dq * Fq, f1b + (size_t)l * Fq, hb, Tq, Fq, Dq);
        gemm_tf32_kernel<1, true><<<dim3(Dq / 128, Tq / 128), 256>>>(
            hb, f2w + (size_t)l * Fq * Dq, f2b + (size_t)l * Dq, tb, Tq, Dq, Fq);
        add_ln_kernel<<<Tq, 256>>>(x1, tb, l2g + (size_t)l * Dq, l2b + (size_t)l * Dq, x);
    }

    gemm_tf32_kernel<1, false><<<dim3((Vq + 127) / 128, Tq / 128), 256>>>(
        x, outw, outb, logits, Tq, Vq, Dq);
}